// round 2
// baseline (speedup 1.0000x reference)
#include <cuda_runtime.h>
#include <cstdint>
#include <cstddef>

// Problem constants (from shapes: W is [256, 320] => F=128, K=64, M=12)
#define FDIM 128
#define KDIM 64
#define CDIM 256      // 2F
#define MNBR 12
#define NMAX 100000

// ---------------- scratch (static device globals; no allocation) -------------
__device__ float g_Pself[(size_t)NMAX * CDIM];                 // 102.4 MB
__device__ float g_Pnbr [(size_t)NMAX * CDIM];                 // 102.4 MB
__device__ float g_gated[(size_t)NMAX * MNBR * CDIM];          // 1228.8 MB
__device__ float g_nbrsum[(size_t)NMAX * FDIM];                // 51.2 MB
__device__ float g_sum1[CDIM], g_sq1[CDIM], g_scale1[CDIM], g_shift1[CDIM];
__device__ float g_sum2[FDIM], g_sq2[FDIM], g_scale2[FDIM], g_shift2[FDIM];
__device__ int   g_idx_is64;   // 1 if nbr_fea_idx is int64, 0 if int32

// ---------------- f32x2 (FFMA2) helpers --------------------------------------
union F4U { float4 f; unsigned long long u[2]; };

__device__ __forceinline__ unsigned long long fma2(unsigned long long a,
                                                   unsigned long long b,
                                                   unsigned long long c) {
    unsigned long long d;
    asm("fma.rn.f32x2 %0, %1, %2, %3;" : "=l"(d) : "l"(a), "l"(b), "l"(c));
    return d;
}
__device__ __forceinline__ float2 unpack2(unsigned long long u) {
    float2 r;
    asm("mov.b64 {%0, %1}, %2;" : "=f"(r.x), "=f"(r.y) : "l"(u));
    return r;
}

// ---------------- K0: zero stats + detect index dtype ------------------------
// int64 little-endian indices (< 2^31) have all odd 32-bit words == 0.
// int32 indices at odd positions are random in [0, N) -> nonzero w.h.p.
__global__ void k_zero(const int* __restrict__ idx32) {
    int t = threadIdx.x;
    if (t < CDIM) { g_sum1[t] = 0.f; g_sq1[t] = 0.f; }
    if (t < FDIM) { g_sum2[t] = 0.f; g_sq2[t] = 0.f; }
    if (t == 0) {
        int odd_nonzero = 0;
        #pragma unroll 4
        for (int i = 1; i < 128; i += 2) odd_nonzero |= (idx32[i] != 0);
        g_idx_is64 = odd_nonzero ? 0 : 1;
    }
}

// ---------------- K1: P_self / P_nbr projection GEMM -------------------------
// grid (ceil(N/32), 2), block 512. part=blockIdx.y: 0 -> P_self (W[:,0:128]),
// 1 -> P_nbr (W[:,128:256]). Thread owns channel c = tid&255, k-half h = tid>>8.
__global__ void __launch_bounds__(512) k_proj(const float* __restrict__ atom,
                                              const float* __restrict__ W, int N) {
    __shared__ __align__(16) float sA[32 * FDIM];   // 16 KB
    __shared__ float sPs[32 * CDIM];                // 32 KB (h==1 half partials)
    const int tid  = threadIdx.x;
    const int c    = tid & 255;
    const int h    = tid >> 8;
    const int part = blockIdx.y;
    const int n0   = blockIdx.x * 32;

    // W[c, part*128 + h*64 + 0..63] into 32 f32x2 registers
    unsigned long long w2[32];
    {
        const float* wp = W + (size_t)c * 320 + part * 128 + h * 64;
        #pragma unroll
        for (int i = 0; i < 16; i++) {
            F4U v; v.f = *(const float4*)(wp + 4 * i);
            w2[2 * i] = v.u[0]; w2[2 * i + 1] = v.u[1];
        }
    }
    // 32 atom rows into smem
    for (int i = tid; i < 32 * FDIM; i += 512) {
        int a = i >> 7, k = i & 127, n = n0 + a;
        sA[i] = (n < N) ? atom[(size_t)n * FDIM + k] : 0.f;
    }
    __syncthreads();

    float res[32];
    #pragma unroll 4
    for (int a = 0; a < 32; a++) {
        const float* av = sA + a * FDIM + h * 64;
        unsigned long long a0 = 0ull, a1 = 0ull;
        #pragma unroll
        for (int i = 0; i < 16; i++) {
            F4U v; v.f = *(const float4*)(av + 4 * i);
            a0 = fma2(w2[2 * i],     v.u[0], a0);
            a1 = fma2(w2[2 * i + 1], v.u[1], a1);
        }
        float2 f0 = unpack2(a0), f1 = unpack2(a1);
        res[a] = (f0.x + f0.y) + (f1.x + f1.y);
    }
    if (h) {
        #pragma unroll
        for (int a = 0; a < 32; a++) sPs[a * CDIM + c] = res[a];
    }
    __syncthreads();
    if (!h) {
        float* out = part ? g_Pnbr : g_Pself;
        #pragma unroll
        for (int a = 0; a < 32; a++) {
            int n = n0 + a;
            if (n < N) out[(size_t)n * CDIM + c] = res[a] + sPs[a * CDIM + c];
        }
    }
}

// ---------------- K2: per-edge GEMM + assemble gated + BN1 partial stats -----
// grid ceil(N/8), block 256. Thread owns channel c = tid. 8 atoms/block.
__global__ void __launch_bounds__(256) k_edge(const float* __restrict__ nbr,
                                              const void* __restrict__ idx_raw,
                                              const float* __restrict__ W,
                                              const float* __restrict__ bias, int N) {
    __shared__ __align__(16) float sNbr[8 * MNBR * KDIM];  // 24 KB
    __shared__ int sIdx[8 * MNBR];
    const int tid = threadIdx.x;
    const int n0  = blockIdx.x * 8;

    // W3 row: W[c, 256 + 0..63] into 32 f32x2 registers
    unsigned long long w2[32];
    {
        const float* wp = W + (size_t)tid * 320 + 256;
        #pragma unroll
        for (int i = 0; i < 16; i++) {
            F4U v; v.f = *(const float4*)(wp + 4 * i);
            w2[2 * i] = v.u[0]; w2[2 * i + 1] = v.u[1];
        }
    }
    // edge features + neighbor indices for 8 atoms
    {
        int avail = N - n0; if (avail > 8) avail = 8;
        int lim4 = avail * MNBR * (KDIM / 4);
        const float4* src = (const float4*)(nbr + (size_t)n0 * MNBR * KDIM);
        float4* dst = (float4*)sNbr;
        for (int i = tid; i < 8 * MNBR * (KDIM / 4); i += 256)
            dst[i] = (i < lim4) ? src[i] : make_float4(0.f, 0.f, 0.f, 0.f);
        const int is64 = g_idx_is64;
        for (int i = tid; i < 8 * MNBR; i += 256) {
            int v = 0;
            if (i < avail * MNBR) {
                if (is64) v = (int)((const long long*)idx_raw)[(size_t)n0 * MNBR + i];
                else      v = ((const int*)idx_raw)[(size_t)n0 * MNBR + i];
            }
            sIdx[i] = v;
        }
    }
    __syncthreads();

    const float b = bias[tid];
    float lsum = 0.f, lsq = 0.f;
    for (int a = 0; a < 8; a++) {
        const int n = n0 + a;
        if (n >= N) break;
        float s = g_Pself[(size_t)n * CDIM + tid];
        float p[MNBR];
        #pragma unroll
        for (int m = 0; m < MNBR; m++)                     // MLP=12 gathers in flight
            p[m] = g_Pnbr[(size_t)sIdx[a * MNBR + m] * CDIM + tid];
        float* grow = g_gated + (size_t)n * MNBR * CDIM + tid;
        #pragma unroll
        for (int m = 0; m < MNBR; m++) {
            const float* ev = sNbr + (a * MNBR + m) * KDIM;
            unsigned long long a0 = 0ull, a1 = 0ull;
            #pragma unroll
            for (int i = 0; i < 16; i++) {
                F4U v; v.f = *(const float4*)(ev + 4 * i);
                a0 = fma2(w2[2 * i],     v.u[0], a0);
                a1 = fma2(w2[2 * i + 1], v.u[1], a1);
            }
            float2 f0 = unpack2(a0), f1 = unpack2(a1);
            float g = (f0.x + f0.y) + (f1.x + f1.y) + s + p[m] + b;
            grow[(size_t)m * CDIM] = g;
            lsum += g; lsq += g * g;
        }
    }
    atomicAdd(&g_sum1[tid], lsum);
    atomicAdd(&g_sq1[tid], lsq);
}

// ---------------- K3: finalize BN1 -------------------------------------------
__global__ void k_fin1(const float* __restrict__ gamma, const float* __restrict__ beta,
                       float invcnt) {
    int c = threadIdx.x;
    float mean = g_sum1[c] * invcnt;
    float var  = g_sq1[c] * invcnt - mean * mean;
    float sc   = gamma[c] * rsqrtf(var + 1e-5f);
    g_scale1[c] = sc;
    g_shift1[c] = beta[c] - mean * sc;
}

// ---------------- K4: gate + neighbor sum + BN2 partial stats ----------------
// grid ceil(N/32), block 256 (2 groups x 128 channels).
__global__ void __launch_bounds__(256) k_sum(int N) {
    const int f = threadIdx.x & 127;
    const int g = threadIdx.x >> 7;
    const int n0 = blockIdx.x * 32;
    const float sc1f = g_scale1[f],       sh1f = g_shift1[f];
    const float sc1c = g_scale1[f + 128], sh1c = g_shift1[f + 128];
    float lsum = 0.f, lsq = 0.f;
    for (int a = g; a < 32; a += 2) {
        const int n = n0 + a;
        if (n >= N) break;
        const float* row = g_gated + (size_t)n * MNBR * CDIM;
        float acc = 0.f;
        #pragma unroll
        for (int m = 0; m < MNBR; m++) {
            float gf = row[(size_t)m * CDIM + f]       * sc1f + sh1f;
            float gc = row[(size_t)m * CDIM + 128 + f] * sc1c + sh1c;
            float sig = 1.f / (1.f + expf(-gf));
            acc += sig * (gc > 0.f ? gc : 0.f);
        }
        g_nbrsum[(size_t)n * FDIM + f] = acc;
        lsum += acc; lsq += acc * acc;
    }
    atomicAdd(&g_sum2[f], lsum);
    atomicAdd(&g_sq2[f], lsq);
}

// ---------------- K5: finalize BN2 -------------------------------------------
__global__ void k_fin2(const float* __restrict__ gamma, const float* __restrict__ beta,
                       float invcnt) {
    int c = threadIdx.x;
    float mean = g_sum2[c] * invcnt;
    float var  = g_sq2[c] * invcnt - mean * mean;
    float sc   = gamma[c] * rsqrtf(var + 1e-5f);
    g_scale2[c] = sc;
    g_shift2[c] = beta[c] - mean * sc;
}

// ---------------- K6: residual + relu ----------------------------------------
__global__ void k_out(const float* __restrict__ atom, float* __restrict__ out, int total) {
    int i = blockIdx.x * blockDim.x + threadIdx.x;
    if (i < total) {
        int f = i & 127;
        float v = atom[i] + g_nbrsum[i] * g_scale2[f] + g_shift2[f];
        out[i] = v > 0.f ? v : 0.f;
    }
}

// ---------------- launch ------------------------------------------------------
extern "C" void kernel_launch(void* const* d_in, const int* in_sizes, int n_in,
                              void* d_out, int out_size) {
    const float* atom = (const float*)d_in[0];
    const float* nbr  = (const float*)d_in[1];
    const void*  idx  = d_in[2];
    const float* W    = (const float*)d_in[3];
    const float* b    = (const float*)d_in[4];
    const float* g1   = (const float*)d_in[5];
    const float* b1   = (const float*)d_in[6];
    const float* g2   = (const float*)d_in[7];
    const float* b2   = (const float*)d_in[8];
    float* out = (float*)d_out;
    const int N = in_sizes[0] / FDIM;

    k_zero<<<1, 256>>>((const int*)idx);
    dim3 gp((N + 31) / 32, 2);
    k_proj<<<gp, 512>>>(atom, W, N);
    k_edge<<<(N + 7) / 8, 256>>>(nbr, idx, W, b, N);
    k_fin1<<<1, CDIM>>>(g1, b1, 1.f / ((float)N * (float)MNBR));
    k_sum<<<(N + 31) / 32, 256>>>(N);
    k_fin2<<<1, FDIM>>>(g2, b2, 1.f / (float)N);
    k_out<<<((size_t)N * FDIM + 255) / 256, 256>>>(atom, out, N * FDIM);
}

// round 3
// speedup vs baseline: 1.0000x; 1.0000x over previous
#include <cuda_runtime.h>
#include <cstdint>
#include <cstddef>

// Problem constants (from shapes: W is [256, 320] => F=128, K=64, M=12)
#define FDIM 128
#define KDIM 64
#define CDIM 256      // 2F
#define MNBR 12
#define NMAX 100000

// ---------------- scratch (static device globals; no allocation) -------------
__device__ float g_Pself[(size_t)NMAX * CDIM];                 // 102.4 MB
__device__ float g_Pnbr [(size_t)NMAX * CDIM];                 // 102.4 MB
__device__ float g_gated[(size_t)NMAX * MNBR * CDIM];          // 1228.8 MB
__device__ float g_nbrsum[(size_t)NMAX * FDIM];                // 51.2 MB
__device__ float g_sum1[CDIM], g_sq1[CDIM], g_scale1[CDIM], g_shift1[CDIM];
__device__ float g_sum2[FDIM], g_sq2[FDIM], g_scale2[FDIM], g_shift2[FDIM];
__device__ int   g_idx_is64;   // 1 if nbr_fea_idx is int64, 0 if int32

// ---------------- f32x2 (FFMA2) helpers --------------------------------------
union F4U { float4 f; unsigned long long u[2]; };

__device__ __forceinline__ unsigned long long fma2(unsigned long long a,
                                                   unsigned long long b,
                                                   unsigned long long c) {
    unsigned long long d;
    asm("fma.rn.f32x2 %0, %1, %2, %3;" : "=l"(d) : "l"(a), "l"(b), "l"(c));
    return d;
}
__device__ __forceinline__ float2 unpack2(unsigned long long u) {
    float2 r;
    asm("mov.b64 {%0, %1}, %2;" : "=f"(r.x), "=f"(r.y) : "l"(u));
    return r;
}

// ---------------- K0: zero stats + detect index dtype ------------------------
// int64 little-endian indices (< 2^31) have all odd 32-bit words == 0.
// int32 indices at odd positions are random in [0, N) -> nonzero w.h.p.
__global__ void k_zero(const int* __restrict__ idx32) {
    int t = threadIdx.x;
    if (t < CDIM) { g_sum1[t] = 0.f; g_sq1[t] = 0.f; }
    if (t < FDIM) { g_sum2[t] = 0.f; g_sq2[t] = 0.f; }
    if (t == 0) {
        int odd_nonzero = 0;
        #pragma unroll 4
        for (int i = 1; i < 128; i += 2) odd_nonzero |= (idx32[i] != 0);
        g_idx_is64 = odd_nonzero ? 0 : 1;
    }
}

// ---------------- K1: P_self / P_nbr projection GEMM -------------------------
// grid (ceil(N/32), 2), block 512. part=blockIdx.y: 0 -> P_self (W[:,0:128]),
// 1 -> P_nbr (W[:,128:256]). Thread owns channel c = tid&255, k-half h = tid>>8.
__global__ void __launch_bounds__(512) k_proj(const float* __restrict__ atom,
                                              const float* __restrict__ W, int N) {
    __shared__ __align__(16) float sA[32 * FDIM];   // 16 KB
    __shared__ float sPs[32 * CDIM];                // 32 KB (h==1 half partials)
    const int tid  = threadIdx.x;
    const int c    = tid & 255;
    const int h    = tid >> 8;
    const int part = blockIdx.y;
    const int n0   = blockIdx.x * 32;

    // W[c, part*128 + h*64 + 0..63] into 32 f32x2 registers
    unsigned long long w2[32];
    {
        const float* wp = W + (size_t)c * 320 + part * 128 + h * 64;
        #pragma unroll
        for (int i = 0; i < 16; i++) {
            F4U v; v.f = *(const float4*)(wp + 4 * i);
            w2[2 * i] = v.u[0]; w2[2 * i + 1] = v.u[1];
        }
    }
    // 32 atom rows into smem
    for (int i = tid; i < 32 * FDIM; i += 512) {
        int a = i >> 7, k = i & 127, n = n0 + a;
        sA[i] = (n < N) ? atom[(size_t)n * FDIM + k] : 0.f;
    }
    __syncthreads();

    float res[32];
    #pragma unroll 4
    for (int a = 0; a < 32; a++) {
        const float* av = sA + a * FDIM + h * 64;
        unsigned long long a0 = 0ull, a1 = 0ull;
        #pragma unroll
        for (int i = 0; i < 16; i++) {
            F4U v; v.f = *(const float4*)(av + 4 * i);
            a0 = fma2(w2[2 * i],     v.u[0], a0);
            a1 = fma2(w2[2 * i + 1], v.u[1], a1);
        }
        float2 f0 = unpack2(a0), f1 = unpack2(a1);
        res[a] = (f0.x + f0.y) + (f1.x + f1.y);
    }
    if (h) {
        #pragma unroll
        for (int a = 0; a < 32; a++) sPs[a * CDIM + c] = res[a];
    }
    __syncthreads();
    if (!h) {
        float* out = part ? g_Pnbr : g_Pself;
        #pragma unroll
        for (int a = 0; a < 32; a++) {
            int n = n0 + a;
            if (n < N) out[(size_t)n * CDIM + c] = res[a] + sPs[a * CDIM + c];
        }
    }
}

// ---------------- K2: per-edge GEMM + assemble gated + BN1 partial stats -----
// grid ceil(N/8), block 256. Thread owns channel c = tid. 8 atoms/block.
__global__ void __launch_bounds__(256) k_edge(const float* __restrict__ nbr,
                                              const void* __restrict__ idx_raw,
                                              const float* __restrict__ W,
                                              const float* __restrict__ bias, int N) {
    __shared__ __align__(16) float sNbr[8 * MNBR * KDIM];  // 24 KB
    __shared__ int sIdx[8 * MNBR];
    const int tid = threadIdx.x;
    const int n0  = blockIdx.x * 8;

    // W3 row: W[c, 256 + 0..63] into 32 f32x2 registers
    unsigned long long w2[32];
    {
        const float* wp = W + (size_t)tid * 320 + 256;
        #pragma unroll
        for (int i = 0; i < 16; i++) {
            F4U v; v.f = *(const float4*)(wp + 4 * i);
            w2[2 * i] = v.u[0]; w2[2 * i + 1] = v.u[1];
        }
    }
    // edge features + neighbor indices for 8 atoms
    {
        int avail = N - n0; if (avail > 8) avail = 8;
        int lim4 = avail * MNBR * (KDIM / 4);
        const float4* src = (const float4*)(nbr + (size_t)n0 * MNBR * KDIM);
        float4* dst = (float4*)sNbr;
        for (int i = tid; i < 8 * MNBR * (KDIM / 4); i += 256)
            dst[i] = (i < lim4) ? src[i] : make_float4(0.f, 0.f, 0.f, 0.f);
        const int is64 = g_idx_is64;
        for (int i = tid; i < 8 * MNBR; i += 256) {
            int v = 0;
            if (i < avail * MNBR) {
                if (is64) v = (int)((const long long*)idx_raw)[(size_t)n0 * MNBR + i];
                else      v = ((const int*)idx_raw)[(size_t)n0 * MNBR + i];
            }
            sIdx[i] = v;
        }
    }
    __syncthreads();

    const float b = bias[tid];
    float lsum = 0.f, lsq = 0.f;
    for (int a = 0; a < 8; a++) {
        const int n = n0 + a;
        if (n >= N) break;
        float s = g_Pself[(size_t)n * CDIM + tid];
        float p[MNBR];
        #pragma unroll
        for (int m = 0; m < MNBR; m++)                     // MLP=12 gathers in flight
            p[m] = g_Pnbr[(size_t)sIdx[a * MNBR + m] * CDIM + tid];
        float* grow = g_gated + (size_t)n * MNBR * CDIM + tid;
        #pragma unroll
        for (int m = 0; m < MNBR; m++) {
            const float* ev = sNbr + (a * MNBR + m) * KDIM;
            unsigned long long a0 = 0ull, a1 = 0ull;
            #pragma unroll
            for (int i = 0; i < 16; i++) {
                F4U v; v.f = *(const float4*)(ev + 4 * i);
                a0 = fma2(w2[2 * i],     v.u[0], a0);
                a1 = fma2(w2[2 * i + 1], v.u[1], a1);
            }
            float2 f0 = unpack2(a0), f1 = unpack2(a1);
            float g = (f0.x + f0.y) + (f1.x + f1.y) + s + p[m] + b;
            grow[(size_t)m * CDIM] = g;
            lsum += g; lsq += g * g;
        }
    }
    atomicAdd(&g_sum1[tid], lsum);
    atomicAdd(&g_sq1[tid], lsq);
}

// ---------------- K3: finalize BN1 -------------------------------------------
__global__ void k_fin1(const float* __restrict__ gamma, const float* __restrict__ beta,
                       float invcnt) {
    int c = threadIdx.x;
    float mean = g_sum1[c] * invcnt;
    float var  = g_sq1[c] * invcnt - mean * mean;
    float sc   = gamma[c] * rsqrtf(var + 1e-5f);
    g_scale1[c] = sc;
    g_shift1[c] = beta[c] - mean * sc;
}

// ---------------- K4: gate + neighbor sum + BN2 partial stats ----------------
// grid ceil(N/32), block 256 (2 groups x 128 channels).
__global__ void __launch_bounds__(256) k_sum(int N) {
    const int f = threadIdx.x & 127;
    const int g = threadIdx.x >> 7;
    const int n0 = blockIdx.x * 32;
    const float sc1f = g_scale1[f],       sh1f = g_shift1[f];
    const float sc1c = g_scale1[f + 128], sh1c = g_shift1[f + 128];
    float lsum = 0.f, lsq = 0.f;
    for (int a = g; a < 32; a += 2) {
        const int n = n0 + a;
        if (n >= N) break;
        const float* row = g_gated + (size_t)n * MNBR * CDIM;
        float acc = 0.f;
        #pragma unroll
        for (int m = 0; m < MNBR; m++) {
            float gf = row[(size_t)m * CDIM + f]       * sc1f + sh1f;
            float gc = row[(size_t)m * CDIM + 128 + f] * sc1c + sh1c;
            float sig = 1.f / (1.f + expf(-gf));
            acc += sig * (gc > 0.f ? gc : 0.f);
        }
        g_nbrsum[(size_t)n * FDIM + f] = acc;
        lsum += acc; lsq += acc * acc;
    }
    atomicAdd(&g_sum2[f], lsum);
    atomicAdd(&g_sq2[f], lsq);
}

// ---------------- K5: finalize BN2 -------------------------------------------
__global__ void k_fin2(const float* __restrict__ gamma, const float* __restrict__ beta,
                       float invcnt) {
    int c = threadIdx.x;
    float mean = g_sum2[c] * invcnt;
    float var  = g_sq2[c] * invcnt - mean * mean;
    float sc   = gamma[c] * rsqrtf(var + 1e-5f);
    g_scale2[c] = sc;
    g_shift2[c] = beta[c] - mean * sc;
}

// ---------------- K6: residual + relu ----------------------------------------
__global__ void k_out(const float* __restrict__ atom, float* __restrict__ out, int total) {
    int i = blockIdx.x * blockDim.x + threadIdx.x;
    if (i < total) {
        int f = i & 127;
        float v = atom[i] + g_nbrsum[i] * g_scale2[f] + g_shift2[f];
        out[i] = v > 0.f ? v : 0.f;
    }
}

// ---------------- launch ------------------------------------------------------
extern "C" void kernel_launch(void* const* d_in, const int* in_sizes, int n_in,
                              void* d_out, int out_size) {
    const float* atom = (const float*)d_in[0];
    const float* nbr  = (const float*)d_in[1];
    const void*  idx  = d_in[2];
    const float* W    = (const float*)d_in[3];
    const float* b    = (const float*)d_in[4];
    const float* g1   = (const float*)d_in[5];
    const float* b1   = (const float*)d_in[6];
    const float* g2   = (const float*)d_in[7];
    const float* b2   = (const float*)d_in[8];
    float* out = (float*)d_out;
    const int N = in_sizes[0] / FDIM;

    k_zero<<<1, 256>>>((const int*)idx);
    dim3 gp((N + 31) / 32, 2);
    k_proj<<<gp, 512>>>(atom, W, N);
    k_edge<<<(N + 7) / 8, 256>>>(nbr, idx, W, b, N);
    k_fin1<<<1, CDIM>>>(g1, b1, 1.f / ((float)N * (float)MNBR));
    k_sum<<<(N + 31) / 32, 256>>>(N);
    k_fin2<<<1, FDIM>>>(g2, b2, 1.f / (float)N);
    k_out<<<((size_t)N * FDIM + 255) / 256, 256>>>(atom, out, N * FDIM);
}